// round 2
// baseline (speedup 1.0000x reference)
#include <cuda_runtime.h>

// QKVAttention: out[b,c,t] = sum_s softmax_s( (q*s)·(k*s) + mask )[t,s] * V[b,c,s]
// N=32, CH=64, T=2048, S=77, L=2125. scale^2 = 1/sqrt(64) = 0.125 folded into Q.

#define CH   64
#define TT   2048
#define SS   77
#define LL   2125
#define TQ   64
#define SKT  64
#define NTH  256

__global__ __launch_bounds__(NTH) void qkv_attn_kernel(
    const float* __restrict__ qkv,
    const float* __restrict__ ekv,
    const float* __restrict__ mask,
    float* __restrict__ out)
{
    // 48KB static smem exactly
    __shared__ float Qs[64 * 64];   // [c][t]   Q tile, pre-scaled
    __shared__ float KPs[64 * 64];  // [c][s] K tile, then aliased as [t][s] P tile
    __shared__ float Vs[64 * 64];   // [s][c] V tile, XOR-swizzled at float4 granularity

    const int tid  = threadIdx.x;
    const int tx   = tid & 15;      // 0..15 : s-cols (QK) / c-cols (PV)
    const int ty   = tid >> 4;      // 0..15 : t-rows
    const int trow = ty * 4;
    const int scol = tx * 4;

    const int b   = blockIdx.y;
    const int qt0 = blockIdx.x * TQ;

    const float* qp  = qkv + (size_t)b * 3 * CH * TT;
    const float* kp  = qp + CH * TT;
    const float* vp  = qp + 2 * CH * TT;
    const float* ekp = ekv + (size_t)b * 2 * CH * SS;
    const float* evp = ekp + CH * SS;

    // ---- load Q tile, scaled by 1/8 (scale*scale) ----
    for (int i = tid; i < 64 * 64; i += NTH) {
        int c = i >> 6, t = i & 63;
        Qs[i] = qp[c * TT + qt0 + t] * 0.125f;
    }

    // ---- online softmax state ----
    float m_[4], l_[4], o_[4][4];
#pragma unroll
    for (int i = 0; i < 4; i++) {
        m_[i] = -1e30f;
        l_[i] = 0.f;
#pragma unroll
        for (int j = 0; j < 4; j++) o_[i][j] = 0.f;
    }

    const int NTILE = (LL + SKT - 1) / SKT;   // 34
    for (int kt = 0; kt < NTILE; kt++) {
        const int s0 = kt * SKT;
        __syncthreads();   // previous PV done before overwriting KPs / Vs

        // ---- load K tile [c][s] (concat encoder || self) ----
        for (int i = tid; i < 64 * 64; i += NTH) {
            int c = i >> 6, s = i & 63;
            int sg = s0 + s;
            float v = 0.f;
            if (sg < SS)      v = ekp[c * SS + sg];
            else if (sg < LL) v = kp[c * TT + sg - SS];
            KPs[i] = v;
        }
        // ---- load V tile transposed [s][c], float4-group XOR swizzle ----
        for (int i = tid; i < 64 * 64; i += NTH) {
            int c = i >> 6, s = i & 63;
            int sg = s0 + s;
            float v = 0.f;
            if (sg < SS)      v = evp[c * SS + sg];
            else if (sg < LL) v = vp[c * TT + sg - SS];
            Vs[s * 64 + (((c >> 2) ^ (s & 15)) << 2) + (c & 3)] = v;
        }
        __syncthreads();

        // ---- QK^T: acc[i][j] = sum_c Qs[c][trow+i] * KPs[c][scol+j] ----
        float acc[4][4];
#pragma unroll
        for (int i = 0; i < 4; i++)
#pragma unroll
            for (int j = 0; j < 4; j++) acc[i][j] = 0.f;

#pragma unroll 8
        for (int c = 0; c < 64; c++) {
            float4 qf = *(const float4*)&Qs[c * 64 + trow];
            float4 kf = *(const float4*)&KPs[c * 64 + scol];
            acc[0][0] += qf.x * kf.x; acc[0][1] += qf.x * kf.y; acc[0][2] += qf.x * kf.z; acc[0][3] += qf.x * kf.w;
            acc[1][0] += qf.y * kf.x; acc[1][1] += qf.y * kf.y; acc[1][2] += qf.y * kf.z; acc[1][3] += qf.y * kf.w;
            acc[2][0] += qf.z * kf.x; acc[2][1] += qf.z * kf.y; acc[2][2] += qf.z * kf.z; acc[2][3] += qf.z * kf.w;
            acc[3][0] += qf.w * kf.x; acc[3][1] += qf.w * kf.y; acc[3][2] += qf.w * kf.z; acc[3][3] += qf.w * kf.w;
        }

        // ---- mask + OOB, online softmax update ----
#pragma unroll
        for (int i = 0; i < 4; i++) {
            const int tg = qt0 + trow + i;
#pragma unroll
            for (int j = 0; j < 4; j++) {
                int sg = s0 + scol + j;
                if (sg < LL) acc[i][j] += mask[(size_t)tg * LL + sg];
                else         acc[i][j] = -1e30f;
            }
        }

#pragma unroll
        for (int i = 0; i < 4; i++) {
            float tm = fmaxf(fmaxf(acc[i][0], acc[i][1]), fmaxf(acc[i][2], acc[i][3]));
            tm = fmaxf(tm, __shfl_xor_sync(0xffffffffu, tm, 8));
            tm = fmaxf(tm, __shfl_xor_sync(0xffffffffu, tm, 4));
            tm = fmaxf(tm, __shfl_xor_sync(0xffffffffu, tm, 2));
            tm = fmaxf(tm, __shfl_xor_sync(0xffffffffu, tm, 1));
            float mn = fmaxf(m_[i], tm);
            float al = __expf(m_[i] - mn);
            float rs = 0.f;
#pragma unroll
            for (int j = 0; j < 4; j++) {
                acc[i][j] = __expf(acc[i][j] - mn);
                rs += acc[i][j];
            }
            rs += __shfl_xor_sync(0xffffffffu, rs, 8);
            rs += __shfl_xor_sync(0xffffffffu, rs, 4);
            rs += __shfl_xor_sync(0xffffffffu, rs, 2);
            rs += __shfl_xor_sync(0xffffffffu, rs, 1);
            l_[i] = l_[i] * al + rs;
            m_[i] = mn;
#pragma unroll
            for (int j = 0; j < 4; j++) o_[i][j] *= al;
        }

        // ---- write P into KPs (aliased over K) ----
        __syncthreads();
#pragma unroll
        for (int i = 0; i < 4; i++) {
            float4 pv = make_float4(acc[i][0], acc[i][1], acc[i][2], acc[i][3]);
            *(float4*)&KPs[(trow + i) * 64 + scol] = pv;
        }
        __syncthreads();

        // ---- PV: o[i][j] += sum_s P[trow+i][s] * V[s][scol+j] ----
#pragma unroll 8
        for (int s = 0; s < 64; s++) {
            float4 vf = *(const float4*)&Vs[s * 64 + ((tx ^ (s & 15)) << 2)];
            float p0 = KPs[(trow + 0) * 64 + s];
            float p1 = KPs[(trow + 1) * 64 + s];
            float p2 = KPs[(trow + 2) * 64 + s];
            float p3 = KPs[(trow + 3) * 64 + s];
            o_[0][0] += p0 * vf.x; o_[0][1] += p0 * vf.y; o_[0][2] += p0 * vf.z; o_[0][3] += p0 * vf.w;
            o_[1][0] += p1 * vf.x; o_[1][1] += p1 * vf.y; o_[1][2] += p1 * vf.z; o_[1][3] += p1 * vf.w;
            o_[2][0] += p2 * vf.x; o_[2][1] += p2 * vf.y; o_[2][2] += p2 * vf.z; o_[2][3] += p2 * vf.w;
            o_[3][0] += p3 * vf.x; o_[3][1] += p3 * vf.y; o_[3][2] += p3 * vf.z; o_[3][3] += p3 * vf.w;
        }
    }

    // ---- normalize + store out[b, c, t] ----
    float inv[4];
#pragma unroll
    for (int i = 0; i < 4; i++) inv[i] = 1.f / l_[i];
    float* op = out + (size_t)b * CH * TT;
#pragma unroll
    for (int j = 0; j < 4; j++) {
        float4 r = make_float4(o_[0][j] * inv[0], o_[1][j] * inv[1],
                               o_[2][j] * inv[2], o_[3][j] * inv[3]);
        *(float4*)&op[(scol + j) * TT + qt0 + trow] = r;
    }
}

extern "C" void kernel_launch(void* const* d_in, const int* in_sizes, int n_in,
                              void* d_out, int out_size) {
    const float* qkv  = (const float*)d_in[0];
    const float* ekv  = (const float*)d_in[1];
    const float* mask = (const float*)d_in[2];
    float* out = (float*)d_out;

    dim3 grid(TT / TQ, 32);   // (query tiles, batch*heads)
    qkv_attn_kernel<<<grid, NTH>>>(qkv, ekv, mask, out);
}

// round 4
// speedup vs baseline: 3.4322x; 3.4322x over previous
#include <cuda_runtime.h>
#include <cstdint>

// QKVAttention, tf32 mma.sync flash attention.
// out[b,c,t] = sum_s softmax_s( 0.125*Q[b,:,t]·K[b,:,s] + mask[t,s] ) * V[b,c,s]
// N=32, CH=64, T=2048, S_enc=77, L=2125 (padded to 2176 = 34*64).

#define CH    64
#define TT    2048
#define SENC  77
#define LLEN  2125
#define SPAD  2176
#define NB    32
#define BM    128
#define BN    64
#define NTH   256
#define NTILE 34
#define KW    72     // Ksm row stride (floats): conflict-free B-frag loads
#define VW    68     // Vsm row stride
#define PW    68     // Psm row stride
#define QW    136    // Qsm row stride (aliases Psm: 64*136 == 128*68 == 8704)

__device__ float KcatG[NB * CH * SPAD];   // tf32-pre-rounded, zero-padded concat K
__device__ float VcatG[NB * CH * SPAD];   // same for V

__device__ __forceinline__ uint32_t tf32r(float x) {
    uint32_t u;
    asm("cvt.rna.tf32.f32 %0, %1;" : "=r"(u) : "f"(x));
    return u;
}

__device__ __forceinline__ void cp_async16(float* dst, const float* src) {
    uint32_t sa = (uint32_t)__cvta_generic_to_shared(dst);
    asm volatile("cp.async.cg.shared.global [%0], [%1], 16;" :: "r"(sa), "l"(src));
}
__device__ __forceinline__ void cp_commit() { asm volatile("cp.async.commit_group;"); }
template<int N> __device__ __forceinline__ void cp_wait() {
    asm volatile("cp.async.wait_group %0;" :: "n"(N));
}

// D += A(16x8,row) * B(8x8,col) ; tf32 inputs as raw b32, fp32 accum
__device__ __forceinline__ void mma8(float c[4], const float a[4], float b0, float b1) {
    const uint32_t* A = reinterpret_cast<const uint32_t*>(a);
    asm volatile(
        "mma.sync.aligned.m16n8k8.row.col.f32.tf32.tf32.f32 "
        "{%0,%1,%2,%3}, {%4,%5,%6,%7}, {%8,%9}, {%0,%1,%2,%3};"
        : "+f"(c[0]), "+f"(c[1]), "+f"(c[2]), "+f"(c[3])
        : "r"(A[0]), "r"(A[1]), "r"(A[2]), "r"(A[3]),
          "r"(__float_as_uint(b0)), "r"(__float_as_uint(b1)));
}

// ---------------- pre-pass: concat + zero-pad + tf32-round K,V ----------------
__global__ __launch_bounds__(256) void concat_kernel(
    const float* __restrict__ qkv, const float* __restrict__ ekv)
{
    int idx = blockIdx.x * 256 + threadIdx.x;      // over NB*CH*SPAD
    int s = idx % SPAD;
    int c = (idx / SPAD) % CH;
    int b = idx / (SPAD * CH);
    float kv = 0.f, vv = 0.f;
    if (s < SENC) {
        const float* e = ekv + ((size_t)b * 2 * CH) * SENC;
        kv = e[c * SENC + s];
        vv = e[(CH + c) * SENC + s];
    } else if (s < LLEN) {
        const float* base = qkv + (size_t)b * 3 * CH * TT + (s - SENC);
        kv = base[(CH + c) * TT];
        vv = base[(2 * CH + c) * TT];
    }
    KcatG[idx] = __uint_as_float(tf32r(kv));
    VcatG[idx] = __uint_as_float(tf32r(vv));
}

// ---------------- main attention kernel ----------------
__global__ __launch_bounds__(NTH) void attn_kernel(
    const float* __restrict__ qkv, const float* __restrict__ mask,
    float* __restrict__ out)
{
    extern __shared__ float smbuf[];
    float* Ksm = smbuf;                    // 2 * 64 * KW
    float* Vsm = Ksm + 2 * 64 * KW;        // 2 * 64 * VW
    float* Psm = Vsm + 2 * 64 * VW;        // 128 * PW   (aliased as Qsm[64][QW])
    float* Qsm = Psm;

    const int tid  = threadIdx.x;
    const int warp = tid >> 5;
    const int lane = tid & 31;
    const int tg   = lane >> 2;   // 0..7
    const int tm   = lane & 3;    // 0..3
    const int b    = blockIdx.y;
    const int qt0  = blockIdx.x * BM;
    const int m0   = warp * 16;

    // ---- stage Q (scaled by 1/8) into Qsm[c][t] ----
    {
        const float* qp = qkv + (size_t)b * 3 * CH * TT + qt0;
#pragma unroll
        for (int it = 0; it < 8; it++) {
            int e4 = it * 256 + tid;          // 2048 float4s
            int c  = e4 >> 5;
            int t4 = (e4 & 31) << 2;
            float4 v = *(const float4*)&qp[c * TT + t4];
            v.x *= 0.125f; v.y *= 0.125f; v.z *= 0.125f; v.w *= 0.125f;
            *(float4*)&Qsm[c * QW + t4] = v;
        }
    }
    __syncthreads();

    // ---- persistent Q A-fragments (tf32) ----
    float qa[8][4];
#pragma unroll
    for (int kc = 0; kc < 8; kc++) {
        int k0 = kc * 8;
        qa[kc][0] = __uint_as_float(tf32r(Qsm[(k0 + tm    ) * QW + m0 + tg    ]));
        qa[kc][1] = __uint_as_float(tf32r(Qsm[(k0 + tm    ) * QW + m0 + tg + 8]));
        qa[kc][2] = __uint_as_float(tf32r(Qsm[(k0 + tm + 4) * QW + m0 + tg    ]));
        qa[kc][3] = __uint_as_float(tf32r(Qsm[(k0 + tm + 4) * QW + m0 + tg + 8]));
    }

    // ---- prefetch machinery ----
    // Tile = 64 rows x 64 floats = 1024 x 16B chunks; 256 threads x 4 chunks each.
    // Thread covers row pc, columns pq+{0,16,32,48}.
    const int pc = tid >> 2;             // channel row 0..63
    const int pq = (tid & 3) << 2;       // base float offset 0,4,8,12
    const float* kg = &KcatG[((size_t)b * CH + pc) * SPAD + pq];
    const float* vg = &VcatG[((size_t)b * CH + pc) * SPAD + pq];

    // tile 0 prefetch (full tile: 4 chunks per thread per matrix)
#pragma unroll
    for (int j = 0; j < 4; j++) {
        cp_async16(&Ksm[pc * KW + pq + j * 16], kg + j * 16);
        cp_async16(&Vsm[pc * VW + pq + j * 16], vg + j * 16);
    }
    cp_commit();

    float m_[2] = {-1e30f, -1e30f}, l_[2] = {0.f, 0.f};
    float oacc[8][4];
#pragma unroll
    for (int nc = 0; nc < 8; nc++)
#pragma unroll
        for (int j = 0; j < 4; j++) oacc[nc][j] = 0.f;

    const int row0 = qt0 + m0 + tg;
    const float* mrow0 = mask + (size_t)row0 * LLEN;
    const float* mrow1 = mrow0 + 8 * LLEN;

    for (int kt = 0; kt < NTILE; kt++) {
        const int buf = kt & 1;
        if (kt + 1 < NTILE) {
            const int so = (kt + 1) * BN;
            const int bo = (buf ^ 1);
#pragma unroll
            for (int j = 0; j < 4; j++) {
                cp_async16(&Ksm[bo * 64 * KW + pc * KW + pq + j * 16], kg + so + j * 16);
                cp_async16(&Vsm[bo * 64 * VW + pc * VW + pq + j * 16], vg + so + j * 16);
            }
            cp_commit();
            cp_wait<1>();
        } else {
            cp_wait<0>();
        }
        __syncthreads();

        const float* Kb = Ksm + buf * 64 * KW;
        const float* Vb = Vsm + buf * 64 * VW;

        // ---- S = Q K^T ----
        float sacc[8][4];
#pragma unroll
        for (int nc = 0; nc < 8; nc++)
#pragma unroll
            for (int j = 0; j < 4; j++) sacc[nc][j] = 0.f;

#pragma unroll
        for (int kc = 0; kc < 8; kc++) {
            const int k0 = kc * 8;
#pragma unroll
            for (int nc = 0; nc < 8; nc++) {
                float b0 = Kb[(k0 + tm    ) * KW + nc * 8 + tg];
                float b1 = Kb[(k0 + tm + 4) * KW + nc * 8 + tg];
                mma8(sacc[nc], qa[kc], b0, b1);
            }
        }

        // ---- mask add (+ OOB -> -inf on last tile) ----
        const int s0 = kt * BN;
        if (s0 + BN <= LLEN) {
#pragma unroll
            for (int nc = 0; nc < 8; nc++) {
                int sg = s0 + nc * 8 + 2 * tm;
                sacc[nc][0] += mrow0[sg];
                sacc[nc][1] += mrow0[sg + 1];
                sacc[nc][2] += mrow1[sg];
                sacc[nc][3] += mrow1[sg + 1];
            }
        } else {
#pragma unroll
            for (int nc = 0; nc < 8; nc++) {
                int sg = s0 + nc * 8 + 2 * tm;
                sacc[nc][0] = (sg     < LLEN) ? sacc[nc][0] + mrow0[sg]     : -1e30f;
                sacc[nc][1] = (sg + 1 < LLEN) ? sacc[nc][1] + mrow0[sg + 1] : -1e30f;
                sacc[nc][2] = (sg     < LLEN) ? sacc[nc][2] + mrow1[sg]     : -1e30f;
                sacc[nc][3] = (sg + 1 < LLEN) ? sacc[nc][3] + mrow1[sg + 1] : -1e30f;
            }
        }

        // ---- online softmax (rows tg, tg+8; quad-local reduction) ----
#pragma unroll
        for (int r = 0; r < 2; r++) {
            float mx = -1e30f;
#pragma unroll
            for (int nc = 0; nc < 8; nc++)
                mx = fmaxf(mx, fmaxf(sacc[nc][2 * r], sacc[nc][2 * r + 1]));
            mx = fmaxf(mx, __shfl_xor_sync(0xffffffffu, mx, 1));
            mx = fmaxf(mx, __shfl_xor_sync(0xffffffffu, mx, 2));
            float mn = fmaxf(m_[r], mx);
            float al = __expf(m_[r] - mn);
            float sum = 0.f;
#pragma unroll
            for (int nc = 0; nc < 8; nc++) {
                float p0 = __expf(sacc[nc][2 * r]     - mn);
                float p1 = __expf(sacc[nc][2 * r + 1] - mn);
                sacc[nc][2 * r] = p0; sacc[nc][2 * r + 1] = p1;
                sum += p0 + p1;
            }
            sum += __shfl_xor_sync(0xffffffffu, sum, 1);
            sum += __shfl_xor_sync(0xffffffffu, sum, 2);
            l_[r] = l_[r] * al + sum;
            m_[r] = mn;
#pragma unroll
            for (int nc = 0; nc < 8; nc++) {
                oacc[nc][2 * r]     *= al;
                oacc[nc][2 * r + 1] *= al;
            }
        }

        // ---- P -> smem (tf32-rounded), warp-local ----
#pragma unroll
        for (int nc = 0; nc < 8; nc++) {
            int col = nc * 8 + 2 * tm;
            Psm[(m0 + tg    ) * PW + col    ] = __uint_as_float(tf32r(sacc[nc][0]));
            Psm[(m0 + tg    ) * PW + col + 1] = __uint_as_float(tf32r(sacc[nc][1]));
            Psm[(m0 + tg + 8) * PW + col    ] = __uint_as_float(tf32r(sacc[nc][2]));
            Psm[(m0 + tg + 8) * PW + col + 1] = __uint_as_float(tf32r(sacc[nc][3]));
        }
        __syncwarp();

        // ---- O += P V ----
#pragma unroll
        for (int kc = 0; kc < 8; kc++) {
            const int k0 = kc * 8;
            float pa[4];
            pa[0] = Psm[(m0 + tg    ) * PW + k0 + tm    ];
            pa[1] = Psm[(m0 + tg + 8) * PW + k0 + tm    ];
            pa[2] = Psm[(m0 + tg    ) * PW + k0 + tm + 4];
            pa[3] = Psm[(m0 + tg + 8) * PW + k0 + tm + 4];
#pragma unroll
            for (int nc = 0; nc < 8; nc++) {
                float b0 = Vb[(nc * 8 + tg) * VW + k0 + tm    ];
                float b1 = Vb[(nc * 8 + tg) * VW + k0 + tm + 4];
                mma8(oacc[nc], pa, b0, b1);
            }
        }
        __syncthreads();   // all reads of Kb/Vb done before next prefetch overwrites
    }

    // ---- normalize, stage O into Psm[t][c], coalesced transpose store ----
    const float inv0 = 1.f / l_[0];
    const float inv1 = 1.f / l_[1];
#pragma unroll
    for (int nc = 0; nc < 8; nc++) {
        int col = nc * 8 + 2 * tm;
        Psm[(m0 + tg    ) * PW + col    ] = oacc[nc][0] * inv0;
        Psm[(m0 + tg    ) * PW + col + 1] = oacc[nc][1] * inv0;
        Psm[(m0 + tg + 8) * PW + col    ] = oacc[nc][2] * inv1;
        Psm[(m0 + tg + 8) * PW + col + 1] = oacc[nc][3] * inv1;
    }
    __syncthreads();

    float* op = out + (size_t)b * CH * TT + qt0;
#pragma unroll
    for (int it = 0; it < 32; it++) {
        int e = it * 256 + tid;          // 8192 elems
        int t = e & 127;
        int c = e >> 7;
        op[c * TT + t] = Psm[t * PW + c];
    }
}

extern "C" void kernel_launch(void* const* d_in, const int* in_sizes, int n_in,
                              void* d_out, int out_size) {
    const float* qkv  = (const float*)d_in[0];
    const float* ekv  = (const float*)d_in[1];
    const float* mask = (const float*)d_in[2];
    float* out = (float*)d_out;

    concat_kernel<<<NB * CH * SPAD / 256, 256>>>(qkv, ekv);

    const int smbytes = (2 * 64 * KW + 2 * 64 * VW + 128 * PW) * 4;   // 106496
    cudaFuncSetAttribute(attn_kernel, cudaFuncAttributeMaxDynamicSharedMemorySize, smbytes);
    dim3 grid(TT / BM, NB);
    attn_kernel<<<grid, NTH, smbytes>>>(qkv, mask, out);
}